// round 14
// baseline (speedup 1.0000x reference)
#include <cuda_runtime.h>
#include <cuda_fp16.h>
#include <cstdint>

// y = spikes @ V @ U^T
// spikes: [512, 32768] f32   (d_in[0])
// U     : [32768, 64]  f32   (d_in[1])
// V     : [32768, 64]  f32   (d_in[2])
// mask_* inputs unused. out: [512, 32768] f32
//
// mma.sync fp16 with hi/lo split, TWO products: A_hi*B_hi + A_lo*B_hi.
// g2: ALL B tiles for the block preloaded once -> barrier-free mainloop.
// g1: B ring of 3 slots, wait_group 1 (wait always satisfied).
// NOTE: cp.async into a shared buffer may only be issued AFTER the
// __syncthreads() that proves all warps finished reading that buffer.

constexpr int BATCH = 512;
constexpr int NPRE  = 32768;
constexpr int NPOST = 32768;
constexpr int R     = 64;

constexpr int KSPLIT = 64;
constexpr int KCHUNK = NPRE / KSPLIT;   // 512

// ---------------- scratch (allocation-free: device globals) ----------------
__device__ __align__(16) float    g_Zpart[KSPLIT * BATCH * R];   // 8 MB
__device__ __align__(16) uint32_t g_Vh[NPRE * R / 2];            // 4 MB (fp16)
__device__ __align__(16) uint32_t g_Uh[NPOST * R / 2];           // 4 MB (fp16)
__device__ __align__(16) uint32_t g_Zh[BATCH * R / 2];           // 64 KB each
__device__ __align__(16) uint32_t g_Zl[BATCH * R / 2];

// ---------------- helpers ---------------------------------------------------
__device__ __forceinline__ uint32_t smem_u32(const void* p) {
    uint32_t a;
    asm("{ .reg .u64 t; cvta.to.shared.u64 t, %1; cvt.u32.u64 %0, t; }"
        : "=r"(a) : "l"(p));
    return a;
}

// fp16 hi of two floats, packed (elem0 in low half)
__device__ __forceinline__ uint32_t pack2h(float x, float y) {
    uint32_t h;
    asm("cvt.rn.f16x2.f32 %0, %1, %2;" : "=r"(h) : "f"(y), "f"(x));
    return h;
}
// fp16 hi/lo split of two floats (elem0 in low half)
__device__ __forceinline__ void split2h(float x, float y, uint32_t& hp, uint32_t& lp) {
    hp = pack2h(x, y);
    __half2 h = *reinterpret_cast<__half2*>(&hp);
    float2 f = __half22float2(h);
    lp = pack2h(x - f.x, y - f.y);
}

__device__ __forceinline__ void cp16(uint32_t dst, const void* src) {
    asm volatile("cp.async.cg.shared.global [%0], [%1], 16;"
                 :: "r"(dst), "l"(src) : "memory");
}
#define CP_COMMIT() asm volatile("cp.async.commit_group;" ::: "memory")
#define CP_WAIT0()  asm volatile("cp.async.wait_group 0;" ::: "memory")
#define CP_WAIT1()  asm volatile("cp.async.wait_group 1;" ::: "memory")

__device__ __forceinline__ void ldm_x4(uint32_t (&r)[4], uint32_t addr) {
    asm volatile("ldmatrix.sync.aligned.m8n8.x4.shared.b16 {%0,%1,%2,%3}, [%4];"
                 : "=r"(r[0]), "=r"(r[1]), "=r"(r[2]), "=r"(r[3]) : "r"(addr));
}
__device__ __forceinline__ void ldm_x4_t(uint32_t (&r)[4], uint32_t addr) {
    asm volatile("ldmatrix.sync.aligned.m8n8.x4.trans.shared.b16 {%0,%1,%2,%3}, [%4];"
                 : "=r"(r[0]), "=r"(r[1]), "=r"(r[2]), "=r"(r[3]) : "r"(addr));
}
__device__ __forceinline__ void mma16816(float (&d)[4], const uint32_t (&a)[4],
                                         uint32_t b0, uint32_t b1) {
    asm volatile("mma.sync.aligned.m16n8k16.row.col.f32.f16.f16.f32 "
                 "{%0,%1,%2,%3}, {%4,%5,%6,%7}, {%8,%9}, {%0,%1,%2,%3};"
                 : "+f"(d[0]), "+f"(d[1]), "+f"(d[2]), "+f"(d[3])
                 : "r"(a[0]), "r"(a[1]), "r"(a[2]), "r"(a[3]), "r"(b0), "r"(b1));
}

// ===========================================================================
// prep: fp16-hi of V and U (packed pairs), row-major [n][64k] = 128B rows
// ===========================================================================
__global__ void __launch_bounds__(256, 4)
split_vu_hi_kernel(const float* __restrict__ V, const float* __restrict__ U) {
    const int gid = blockIdx.x * 256 + threadIdx.x;       // float4 index
    const float4* src = (blockIdx.y == 0) ? (const float4*)V : (const float4*)U;
    uint2* dh = (blockIdx.y == 0) ? (uint2*)g_Vh : (uint2*)g_Uh;
    float4 v = src[gid];
    dh[gid] = make_uint2(pack2h(v.x, v.y), pack2h(v.z, v.w));
}

// ===========================================================================
// GEMM1: Zpart[ks][b][r] = sum_{k in chunk} spikes[b][k] * V[k][r]
// Tile 128(m) x 64(n=R), K-tile 64, 8 k-tiles.  A double-buffered (split
// in-kernel), B = V_hi in a 3-slot cp.async ring (waits always satisfied).
// smem: Abuf0 [Ah 16K | Al 16K] @0, Abuf1 @32K, B ring 3 x 8K @64K  (88K)
// ===========================================================================
constexpr uint32_t G1_AL = 16384;
constexpr uint32_t G1_B  = 65536;
constexpr int G1_SMEM = 90112;

__global__ void __launch_bounds__(256, 2)
g1_kernel(const float* __restrict__ S) {
    extern __shared__ char sm[];
    const uint32_t sb = smem_u32(sm);
    const int tid = threadIdx.x, lane = tid & 31, w = tid >> 5;
    const int ks = blockIdx.x, mt = blockIdx.y;
    const int mbase = (w >> 1) * 32, nbase = (w & 1) * 32;
    const int kbase = ks * KCHUNK;

    float acc[2][4][4];
#pragma unroll
    for (int i = 0; i < 2; i++)
#pragma unroll
        for (int j = 0; j < 4; j++)
#pragma unroll
            for (int q = 0; q < 4; q++) acc[i][j][q] = 0.f;

    // A staging map: row = (tid>>4) + 16i, seg = tid & 15 (float4 units)
    const int r0 = tid >> 4, seg = tid & 15;
    const float* Sp = S + (size_t)(mt * 128 + r0) * NPRE + kbase + seg * 4;
    const uint32_t sxor = (uint32_t)((r0 & 7) << 4);
    uint32_t a_off[8];
#pragma unroll
    for (int i = 0; i < 8; i++)
        a_off[i] = (uint32_t)(r0 + 16 * i) * 128u + (((uint32_t)seg * 8u) ^ sxor);

    // B cp.async map: 2 chunks of 16B per thread (8 KB tile)
    uint32_t b_dst[2], b_row[2];
#pragma unroll
    for (int i = 0; i < 2; i++) {
        uint32_t ch = (uint32_t)tid + 256u * i;   // 0..511
        uint32_t row = ch >> 3, sg = ch & 7;
        b_row[i] = row * 128u + sg * 16u;
        b_dst[i] = row * 128u + ((sg * 16u) ^ ((row & 7u) << 4));
    }

    const uint32_t lrow  = (uint32_t)(lane & 15) * 128u;
    const uint32_t lhalf = (uint32_t)(lane >> 4) * 16u;
    const uint32_t lx    = (uint32_t)(lane & 7) << 4;

    // prologue: issue B(0) and B(1) into ring slots 0,1; prefetch A(0) regs
    {
        const char* vh = (const char*)g_Vh + (size_t)kbase * 128;
#pragma unroll
        for (int s = 0; s < 2; s++) {
#pragma unroll
            for (int i = 0; i < 2; i++)
                cp16(sb + G1_B + (uint32_t)s * 8192u + b_dst[i],
                     vh + (size_t)s * 64 * 128 + b_row[i]);
            CP_COMMIT();
        }
    }
    float4 ra[8];
#pragma unroll
    for (int i = 0; i < 8; i++) ra[i] = *(const float4*)(Sp + (size_t)i * 16 * NPRE);

#pragma unroll 1
    for (int kt = 0; kt < 8; kt++) {
        const uint32_t abuf = sb + (uint32_t)(kt & 1) * 32768u;
        char* abufc = sm + (uint32_t)(kt & 1) * 32768u;
        const uint32_t bbuf = sb + G1_B + (uint32_t)(kt % 3) * 8192u;

        // store A(kt) hi/lo into A-buf kt&1
#pragma unroll
        for (int i = 0; i < 8; i++) {
            uint32_t h0, l0, h1, l1;
            split2h(ra[i].x, ra[i].y, h0, l0);
            split2h(ra[i].z, ra[i].w, h1, l1);
            *(uint2*)(abufc + a_off[i])         = make_uint2(h0, h1);
            *(uint2*)(abufc + G1_AL + a_off[i]) = make_uint2(l0, l1);
        }
        if (kt < 7) { CP_WAIT1(); } else { CP_WAIT0(); }   // B(kt) done
        __syncthreads();     // all warps done reading A-buf kt&1 / B slot (kt+2)%3

        // refill ring slot (kt+2)%3 (its last readers were iter kt-1); A(kt+1)
        if (kt + 2 < 8) {
            const char* vh = (const char*)g_Vh + ((size_t)kbase + (kt + 2) * 64) * 128;
            const uint32_t ob = sb + G1_B + (uint32_t)((kt + 2) % 3) * 8192u;
#pragma unroll
            for (int i = 0; i < 2; i++)
                cp16(ob + b_dst[i], vh + b_row[i]);
            CP_COMMIT();
        }
        if (kt + 1 < 8) {
            const float* Sk = Sp + (kt + 1) * 64;
#pragma unroll
            for (int i = 0; i < 8; i++) ra[i] = *(const float4*)(Sk + (size_t)i * 16 * NPRE);
        }

        // mma: acc += Ah*Bh (8 indep) then Al*Bh (8 indep)
#pragma unroll
        for (int s = 0; s < 4; s++) {
            const uint32_t c = (uint32_t)s * 32u;
            uint32_t ah[2][4], al[2][4], bh[2][4];
#pragma unroll
            for (int mi = 0; mi < 2; mi++) {
                uint32_t ad = abuf + (uint32_t)(mbase + mi * 16) * 128u
                            + lrow + ((c + lhalf) ^ lx);
                ldm_x4(ah[mi], ad);
                ldm_x4(al[mi], ad + G1_AL);
            }
#pragma unroll
            for (int t = 0; t < 2; t++) {
                uint32_t bd = bbuf + (uint32_t)s * 16u * 128u + lrow
                            + (((uint32_t)(nbase + t * 16) * 2u + lhalf) ^ lx);
                ldm_x4_t(bh[t], bd);
            }
#pragma unroll
            for (int t = 0; t < 2; t++)
#pragma unroll
                for (int mi = 0; mi < 2; mi++) {
                    mma16816(acc[mi][2 * t],     ah[mi], bh[t][0], bh[t][1]);
                    mma16816(acc[mi][2 * t + 1], ah[mi], bh[t][2], bh[t][3]);
                }
#pragma unroll
            for (int t = 0; t < 2; t++)
#pragma unroll
                for (int mi = 0; mi < 2; mi++) {
                    mma16816(acc[mi][2 * t],     al[mi], bh[t][0], bh[t][1]);
                    mma16816(acc[mi][2 * t + 1], al[mi], bh[t][2], bh[t][3]);
                }
        }
    }

    // epilogue -> Zpart
    float* Zb = g_Zpart + ((size_t)ks * BATCH + mt * 128) * R;
#pragma unroll
    for (int mi = 0; mi < 2; mi++)
#pragma unroll
        for (int nt = 0; nt < 4; nt++) {
            int row = mbase + mi * 16 + (lane >> 2);
            int col = nbase + nt * 8 + 2 * (lane & 3);
            *(float2*)(Zb + (size_t)row * R + col) =
                make_float2(acc[mi][nt][0], acc[mi][nt][1]);
            *(float2*)(Zb + (size_t)(row + 8) * R + col) =
                make_float2(acc[mi][nt][2], acc[mi][nt][3]);
        }
}

// ===========================================================================
// reduce + split: Z = sum_ks Zpart; write packed fp16 hi/lo.
// 256 blocks; 4 threads cooperate per output pair via smem (fixed order).
// ===========================================================================
__global__ void __launch_bounds__(256, 4)
reduce_split_kernel() {
    __shared__ float2 s[4][64];
    const int tid = threadIdx.x;
    const int sub = tid >> 6, li = tid & 63;
    const int gid = blockIdx.x * 64 + li;                 // pair index
    const float2* p = (const float2*)g_Zpart;
    float sx = 0.f, sy = 0.f;
#pragma unroll
    for (int k = 0; k < 16; k++) {
        float2 v = p[(size_t)(sub * 16 + k) * (BATCH * R / 2) + gid];
        sx += v.x;
        sy += v.y;
    }
    s[sub][li] = make_float2(sx, sy);
    __syncthreads();
    if (sub == 0) {
        float2 a = s[0][li], b = s[1][li], c = s[2][li], d = s[3][li];
        float fx = (a.x + b.x) + (c.x + d.x);
        float fy = (a.y + b.y) + (c.y + d.y);
        uint32_t h, l;
        split2h(fx, fy, h, l);
        g_Zh[gid] = h;
        g_Zl[gid] = l;
    }
}

// ===========================================================================
// GEMM2: Y[b][n] = sum_r Z[b][r] * U[n][r].
// Persistent over n with ALL B tiles preloaded: block bx covers n-tiles
// bx, bx+74, ... (<=7 tiles, <=56KB).  One stage + one sync, then a
// barrier-free, wait-free mainloop (ldmatrix + mma + STG only).
// smem: Zh@0 (16K) Zl@16K | B tiles @32K (7 x 8K)   (88K per CTA, 2 CTAs/SM)
// ===========================================================================
constexpr int G2_NSTRIDE = 74;
constexpr int G2_NTILES  = NPOST / 64;   // 512
constexpr uint32_t G2_ZL = 16384, G2_B0 = 32768;
constexpr int G2_SMEM = 90112;

__global__ void __launch_bounds__(256, 2)
g2_kernel(float* __restrict__ Y) {
    extern __shared__ char sm[];
    const uint32_t sb = smem_u32(sm);
    const int tid = threadIdx.x, lane = tid & 31, w = tid >> 5;
    const int bx = blockIdx.x, mt = blockIdx.y;
    const int mbase = (w >> 1) * 32, nhalf = w & 1;

    // stage Z (mt) hi/lo: 4 chunks of 16B per half per thread
    {
        const char* zh = (const char*)g_Zh + (size_t)mt * 128 * 128;
        const char* zl = (const char*)g_Zl + (size_t)mt * 128 * 128;
#pragma unroll
        for (int i = 0; i < 4; i++) {
            uint32_t ch = (uint32_t)tid + 256u * i;   // 0..1023
            uint32_t row = ch >> 3, sg = ch & 7;
            uint32_t so = row * 128u + sg * 16u;
            uint32_t dof = row * 128u + ((sg * 16u) ^ ((row & 7u) << 4));
            cp16(sb + dof,         zh + so);
            cp16(sb + G2_ZL + dof, zl + so);
        }
    }
    // stage ALL B tiles for this block (<=7): 2 chunks of 16B per thread each
    {
        uint32_t ch0 = (uint32_t)tid, ch1 = (uint32_t)tid + 256u;
        uint32_t row0 = ch0 >> 3, sg0 = ch0 & 7;
        uint32_t row1 = ch1 >> 3, sg1 = ch1 & 7;
        uint32_t src0 = row0 * 128u + sg0 * 16u;
        uint32_t src1 = row1 * 128u + sg1 * 16u;
        uint32_t dst0 = row0 * 128u + ((sg0 * 16u) ^ ((row0 & 7u) << 4));
        uint32_t dst1 = row1 * 128u + ((sg1 * 16u) ^ ((row1 & 7u) << 4));
        int i = 0;
#pragma unroll 1
        for (int nt = bx; nt < G2_NTILES; nt += G2_NSTRIDE, i++) {
            const char* uh = (const char*)g_Uh + (size_t)nt * 64 * 128;
            uint32_t base = sb + G2_B0 + (uint32_t)i * 8192u;
            cp16(base + dst0, uh + src0);
            cp16(base + dst1, uh + src1);
        }
    }
    CP_COMMIT();

    const uint32_t lrow  = (uint32_t)(lane & 15) * 128u;
    const uint32_t lhalf = (uint32_t)(lane >> 4) * 16u;
    const uint32_t lx    = (uint32_t)(lane & 7) << 4;

    CP_WAIT0();
    __syncthreads();     // the ONLY barrier

    // A fragments -> registers: 32 hi + 32 lo
    uint32_t ahr[4][2][4], alr[4][2][4];
#pragma unroll
    for (int s = 0; s < 4; s++) {
        const uint32_t c = (uint32_t)s * 32u;
#pragma unroll
        for (int mi = 0; mi < 2; mi++) {
            uint32_t ad = sb + (uint32_t)(mbase + mi * 16) * 128u
                        + lrow + ((c + lhalf) ^ lx);
            ldm_x4(ahr[s][mi], ad);
            ldm_x4(alr[s][mi], ad + G2_ZL);
        }
    }

    // barrier-free, wait-free mainloop
    int it = 0;
#pragma unroll 1
    for (int nt = bx; nt < G2_NTILES; nt += G2_NSTRIDE, it++) {
        const uint32_t bufb = sb + G2_B0 + (uint32_t)it * 8192u;

        float acc[2][4][4];
#pragma unroll
        for (int i = 0; i < 2; i++)
#pragma unroll
            for (int j = 0; j < 4; j++)
#pragma unroll
                for (int q = 0; q < 4; q++) acc[i][j][q] = 0.f;

#pragma unroll
        for (int s = 0; s < 4; s++) {
            const uint32_t c = (uint32_t)s * 32u;
            uint32_t bh[2][4];
#pragma unroll
            for (int t = 0; t < 2; t++) {
                uint32_t bd = bufb + (uint32_t)(nhalf * 32 + t * 16) * 128u
                            + lrow + ((c + lhalf) ^ lx);
                ldm_x4(bh[t], bd);
            }
            // reg map: {r0,r2} = n-group 0 (k lo/hi), {r1,r3} = n-group 1
#pragma unroll
            for (int t = 0; t < 2; t++)
#pragma unroll
                for (int mi = 0; mi < 2; mi++) {
                    mma16816(acc[mi][2 * t],     ahr[s][mi], bh[t][0], bh[t][2]);
                    mma16816(acc[mi][2 * t + 1], ahr[s][mi], bh[t][1], bh[t][3]);
                }
#pragma unroll
            for (int t = 0; t < 2; t++)
#pragma unroll
                for (int mi = 0; mi < 2; mi++) {
                    mma16816(acc[mi][2 * t],     alr[s][mi], bh[t][0], bh[t][2]);
                    mma16816(acc[mi][2 * t + 1], alr[s][mi], bh[t][1], bh[t][3]);
                }
        }

        // epilogue -> Y for this n-tile
        float* Yb = Y + (size_t)(mt * 128) * NPOST + nt * 64;
        const int nbase = nhalf * 32;
#pragma unroll
        for (int mi = 0; mi < 2; mi++)
#pragma unroll
            for (int ntj = 0; ntj < 4; ntj++) {
                int row = mbase + mi * 16 + (lane >> 2);
                int col = nbase + ntj * 8 + 2 * (lane & 3);
                *(float2*)(Yb + (size_t)row * NPOST + col) =
                    make_float2(acc[mi][ntj][0], acc[mi][ntj][1]);
                *(float2*)(Yb + (size_t)(row + 8) * NPOST + col) =
                    make_float2(acc[mi][ntj][2], acc[mi][ntj][3]);
            }
    }
}

// ===========================================================================
extern "C" void kernel_launch(void* const* d_in, const int* in_sizes, int n_in,
                              void* d_out, int out_size) {
    const float* spikes = (const float*)d_in[0];   // [512, 32768]
    const float* U      = (const float*)d_in[1];   // [32768, 64]
    const float* V      = (const float*)d_in[2];   // [32768, 64]
    float* Y            = (float*)d_out;           // [512, 32768]

    cudaFuncSetAttribute(g1_kernel, cudaFuncAttributeMaxDynamicSharedMemorySize, G1_SMEM);
    cudaFuncSetAttribute(g2_kernel, cudaFuncAttributeMaxDynamicSharedMemorySize, G2_SMEM);

    split_vu_hi_kernel<<<dim3(NPRE * R / 4 / 256, 2), 256>>>(V, U);
    g1_kernel<<<dim3(KSPLIT, BATCH / 128), 256, G1_SMEM>>>(spikes);
    reduce_split_kernel<<<(BATCH * R / 2) / 64, 256>>>();
    g2_kernel<<<dim3(G2_NSTRIDE, BATCH / 128), 256, G2_SMEM>>>(Y);
}